// round 7
// baseline (speedup 1.0000x reference)
#include <cuda_runtime.h>
#include <cstdint>
#include <math.h>

// Shapes (fixed by the problem)
#define NSENT 4096
#define L     512
#define LQ    32
#define D     30
#define AF    10
#define KK    4

#define TILE_FLOATS (L * D)          // 15360
#define TILE_BYTES  (TILE_FLOATS * 4) // 61440

// Precomputed tables / question-side results
__device__ float g_W1sum[D * D];
__device__ float g_W2sum[D * D];
__device__ float g_A1[D * D * 6];
__device__ float g_qraw[D];
__device__ float g_q1g[D];
__device__ float g_q2g[D];
__device__ float g_inv_nraw, g_inv_n1, g_inv_n2;
__device__ float g_costs[NSENT];
__device__ int   g_ctr;

__device__ __forceinline__ uint32_t smem_u32(const void* p) {
    uint32_t a;
    asm("{ .reg .u64 t; cvta.to.shared.u64 t, %1; cvt.u32.u64 %0, t; }" : "=r"(a) : "l"(p));
    return a;
}

// ---------------------------------------------------------------------------
// Kernel 1 (prep): tables into SMEM + gmem; question side from SMEM.
// ---------------------------------------------------------------------------
__global__ void prep_kernel(const float* __restrict__ qe,
                            const float* __restrict__ w1, const float* __restrict__ b1,
                            const float* __restrict__ w2, const float* __restrict__ b2)
{
    __shared__ float sW1[D * D], sW2[D * D], sA[D * D * 6];
    __shared__ float Sq[32], xbq[6][32], Tq[32];

    int tid = threadIdx.x; // 960
    if (tid == 0) g_ctr = 0;

    if (tid < D * D) {
        const float* w = w1 + tid * KK;
        float w0 = w[0], wv1 = w[1], wv2 = w[2], w3 = w[3];
        float ws = w0 + wv1 + wv2 + w3;
        sW1[tid] = ws; g_W1sum[tid] = ws;
        const float* v = w2 + tid * KK;
        float vs = v[0] + v[1] + v[2] + v[3];
        sW2[tid] = vs; g_W2sum[tid] = vs;
        float a0 = 3.f * w3 + 2.f * wv2 + wv1;
        float a1 = 2.f * w3 + wv2;
        float a2 = w3;
        float a3 = w0;
        float a4 = 2.f * w0 + wv1;
        float a5 = 3.f * w0 + 2.f * wv1 + wv2;
        float* As = sA + tid * 6;  float* Ag = g_A1 + tid * 6;
        As[0] = a0; Ag[0] = a0;  As[1] = a1; Ag[1] = a1;
        As[2] = a2; Ag[2] = a2;  As[3] = a3; Ag[3] = a3;
        As[4] = a4; Ag[4] = a4;  As[5] = a5; Ag[5] = a5;
    }

    if (tid < D) {
        float s = 0.f;
        for (int t = 0; t < LQ; t++) s += qe[t * D + tid];
        Sq[tid] = s;
        xbq[0][tid] = qe[0 * D + tid];
        xbq[1][tid] = qe[1 * D + tid];
        xbq[2][tid] = qe[2 * D + tid];
        xbq[3][tid] = qe[(LQ - 3) * D + tid];
        xbq[4][tid] = qe[(LQ - 2) * D + tid];
        xbq[5][tid] = qe[(LQ - 1) * D + tid];
    }
    __syncthreads();

    if (tid < 32) {
        const int o = tid;
        const float invLq3 = 1.f / (float)(LQ + 3);
        float q1 = 0.f, Tv = 0.f;
        if (o < D) {
            float ds = 0.f, bc = 0.f;
            for (int j = 0; j < D; j++) ds += sW1[o * D + j] * Sq[j];
            for (int j = 0; j < D; j++) {
                const float* A = sA + (o * D + j) * 6;
                #pragma unroll
                for (int m = 0; m < 6; m++) bc += A[m] * xbq[m][j];
            }
            q1 = b1[o] + ds * invLq3;
            Tv = (float)LQ * b1[o] + ds - 0.25f * bc;
        }
        Tq[o] = Tv;
        __syncwarp();

        float q2 = 0.f;
        if (o < D) {
            float d2 = 0.f;
            for (int j = 0; j < D; j++) d2 += sW2[o * D + j] * Tq[j];
            q2 = b2[o] + d2 * invLq3;
            g_qraw[o] = Sq[o];
            g_q1g[o] = q1;
            g_q2g[o] = q2;
        }
        __syncwarp();

        float n0 = (o < D) ? Sq[o] * Sq[o] : 0.f;
        float n1 = q1 * q1;
        float n2 = q2 * q2;
        #pragma unroll
        for (int off = 16; off; off >>= 1) {
            n0 += __shfl_down_sync(0xffffffffu, n0, off);
            n1 += __shfl_down_sync(0xffffffffu, n1, off);
            n2 += __shfl_down_sync(0xffffffffu, n2, off);
        }
        if (o == 0) {
            g_inv_nraw = rsqrtf(n0);
            g_inv_n1 = rsqrtf(n1);
            g_inv_n2 = rsqrtf(n2);
        }
    }
}

// ---------------------------------------------------------------------------
// Fused kernel: TMA bulk-copy the [512,30] tile into smem, reduce from smem,
// tail math on warp 0. One CTA per sentence, 3 CTAs/SM resident.
// ---------------------------------------------------------------------------
#define TPB 480

__global__ __launch_bounds__(TPB, 3) void fused_kernel(
    const float* __restrict__ se, const float* __restrict__ gaf,
    const int* __restrict__ labels,
    const float* __restrict__ b1, const float* __restrict__ b2,
    const float* __restrict__ lw, const float* __restrict__ lb,
    float* __restrict__ out)
{
    extern __shared__ float dyn[];
    float* tile = dyn;                    // 15360 floats (TMA dst; later reused for partials)
    float* sW1  = tile + TILE_FLOATS;     // 900
    float* sW2  = sW1 + D * D;            // 900

    __shared__ __align__(8) uint64_t mbar;
    __shared__ float xb[6 * 32];
    __shared__ float S[32], T[32];
    __shared__ int last;

    const int n = blockIdx.x;
    const int tid = threadIdx.x;
    const uint32_t bar_a = smem_u32(&mbar);
    const uint32_t tile_a = smem_u32(tile);

    if (tid == 0) {
        asm volatile("mbarrier.init.shared.b64 [%0], %1;" :: "r"(bar_a), "r"(1) : "memory");
    }
    __syncthreads();

    if (tid == 0) {
        asm volatile("mbarrier.arrive.expect_tx.shared.b64 _, [%0], %1;"
                     :: "r"(bar_a), "r"((uint32_t)TILE_BYTES) : "memory");
        const float* src = se + (size_t)n * TILE_FLOATS;
        asm volatile("cp.async.bulk.shared::cta.global.mbarrier::complete_tx::bytes [%0], [%1], %2, [%3];"
                     :: "r"(tile_a), "l"(src), "r"((uint32_t)TILE_BYTES), "r"(bar_a) : "memory");
    }

    // Overlap: stage W tables (L2-hot) while TMA fills the tile
    for (int i = tid; i < D * D; i += TPB) { sW1[i] = g_W1sum[i]; sW2[i] = g_W2sum[i]; }

    // Wait for tile
    {
        uint32_t done;
        asm volatile(
            "{\n\t.reg .pred p;\n\t"
            "mbarrier.try_wait.parity.acquire.cta.shared::cta.b64 p, [%1], %2;\n\t"
            "selp.b32 %0, 1, 0, p;\n\t}"
            : "=r"(done) : "r"(bar_a), "r"(0u) : "memory");
        if (!done) {
            asm volatile(
                "{\n\t.reg .pred P1;\n\t"
                "WL_%=:\n\t"
                "mbarrier.try_wait.parity.acquire.cta.shared::cta.b64 P1, [%0], %1, 0x989680;\n\t"
                "@P1 bra.uni WD_%=;\n\t"
                "bra.uni WL_%=;\n\t"
                "WD_%=:\n\t}"
                :: "r"(bar_a), "r"(0u) : "memory");
        }
    }

    // Capture boundary rows BEFORE partials overwrite the tile's low slots
    if (tid < 6 * D) {
        int m = tid / D, j = tid % D;
        int t = (m < 3) ? m : (L - 6 + m);  // 0,1,2,509,510,511
        xb[m * 32 + j] = tile[t * D + j];
    }
    __syncthreads();

    // Reduce 3840 float4s from smem: 8 per thread, then write partial to slot tid.
    // Slot k is only ever read by thread k%480, so writing slot tid is race-free.
    {
        const float4* t4 = reinterpret_cast<const float4*>(tile);
        float4 acc = make_float4(0.f, 0.f, 0.f, 0.f);
        #pragma unroll
        for (int it = 0; it < (TILE_FLOATS / 4) / TPB; it++) {
            float4 v = t4[tid + TPB * it];
            acc.x += v.x; acc.y += v.y; acc.z += v.z; acc.w += v.w;
        }
        reinterpret_cast<float4*>(tile)[tid] = acc;
    }
    __syncthreads();

    if (tid < 32) {
        const int o = tid;
        float s = 0.f;
        if (o < D) {
            #pragma unroll
            for (int k = 0; k < (TPB * 4) / D; k++)   // 64 partials, stride 30
                s += tile[o + D * k];
        }
        S[o] = s;
        __syncwarp();

        const float inv515 = 1.f / (float)(L + 3);
        float s1 = 0.f, Tv = 0.f;
        if (o < D) {
            float ds = 0.f, bc = 0.f;
            #pragma unroll
            for (int j = 0; j < D; j++) ds += sW1[o * D + j] * S[j];
            #pragma unroll
            for (int j = 0; j < D; j++) {
                const float* A = g_A1 + (o * D + j) * 6;
                #pragma unroll
                for (int m = 0; m < 6; m++) bc += A[m] * xb[m * 32 + j];
            }
            s1 = b1[o] + ds * inv515;
            Tv = (float)L * b1[o] + ds - 0.25f * bc;
        }
        T[o] = Tv;
        __syncwarp();

        float s2 = 0.f;
        if (o < D) {
            float d2 = 0.f;
            #pragma unroll
            for (int j = 0; j < D; j++) d2 += sW2[o * D + j] * T[j];
            s2 = b2[o] + d2 * inv515;
        }

        float qr = 0.f, q1v = 0.f, q2v = 0.f;
        if (o < D) { qr = g_qraw[o]; q1v = g_q1g[o]; q2v = g_q2g[o]; }

        float p0 = s * qr, p1 = s * q2v, p2 = s * s;
        float p3 = s1 * q1v, p4 = s1 * s1, p5 = s2 * q2v, p6 = s2 * s2;
        #pragma unroll
        for (int off = 16; off; off >>= 1) {
            p0 += __shfl_down_sync(0xffffffffu, p0, off);
            p1 += __shfl_down_sync(0xffffffffu, p1, off);
            p2 += __shfl_down_sync(0xffffffffu, p2, off);
            p3 += __shfl_down_sync(0xffffffffu, p3, off);
            p4 += __shfl_down_sync(0xffffffffu, p4, off);
            p5 += __shfl_down_sync(0xffffffffu, p5, off);
            p6 += __shfl_down_sync(0xffffffffu, p6, off);
        }
        if (o == 0) {
            float inv_nS = rsqrtf(p2);
            float sim1 = (n == 0) ? (p0 * g_inv_nraw * inv_nS)
                                  : (p1 * g_inv_n2 * inv_nS);
            float sim2 = p3 * rsqrtf(p4) * g_inv_n1;
            float sim3 = p5 * rsqrtf(p6) * g_inv_n2;

            const float* g = gaf + (size_t)n * AF;
            float l0 = lb[0] + lw[0] * sim1 + lw[1] * sim2 + lw[2] * sim3;
            float l1 = lb[1] + lw[13] * sim1 + lw[14] * sim2 + lw[15] * sim3;
            #pragma unroll
            for (int f = 0; f < AF; f++) {
                float gv = g[f];
                l0 += lw[3 + f] * gv;
                l1 += lw[16 + f] * gv;
            }
            float mx = fmaxf(l0, l1);
            float lse = mx + logf(expf(l0 - mx) + expf(l1 - mx));
            float lp0 = l0 - lse, lp1 = l1 - lse;
            float e0 = expf(lp0), e1 = expf(lp1);
            out[1 + n] = e1 / (e0 + e1);
            int lab = labels[n];
            g_costs[n] = -(lab ? lp1 : lp0);
        }
    }

    // Last block: deterministic cost reduction
    __syncthreads();
    if (tid == 0) {
        __threadfence();
        int old = atomicAdd(&g_ctr, 1);
        last = (old == NSENT - 1) ? 1 : 0;
    }
    __syncthreads();
    if (last) {
        __threadfence();
        __shared__ float sm[256];
        if (tid < 256) {
            float s = 0.f;
            for (int i = tid; i < NSENT; i += 256) s += g_costs[i];
            sm[tid] = s;
        }
        __syncthreads();
        for (int w = 128; w; w >>= 1) {
            if (tid < w) sm[tid] += sm[tid + w];
            __syncthreads();
        }
        if (tid == 0) out[0] = sm[0] / (float)NSENT;
    }
}

// ---------------------------------------------------------------------------
extern "C" void kernel_launch(void* const* d_in, const int* in_sizes, int n_in,
                              void* d_out, int out_size)
{
    const float* se  = (const float*)d_in[0];
    const float* qe  = (const float*)d_in[1];
    const float* gaf = (const float*)d_in[2];
    const int*   lab = (const int*)d_in[3];
    const float* w1  = (const float*)d_in[4];
    const float* b1  = (const float*)d_in[5];
    const float* w2  = (const float*)d_in[6];
    const float* b2  = (const float*)d_in[7];
    const float* lw  = (const float*)d_in[8];
    const float* lb  = (const float*)d_in[9];
    float* out = (float*)d_out;

    const int dyn_smem = (TILE_FLOATS + 2 * D * D) * 4;  // tile + sW1 + sW2
    static int configured = 0;
    if (!configured) {
        cudaFuncSetAttribute(fused_kernel, cudaFuncAttributeMaxDynamicSharedMemorySize, dyn_smem);
        configured = 1;
    }

    prep_kernel<<<1, 960>>>(qe, w1, b1, w2, b2);
    fused_kernel<<<NSENT, TPB, dyn_smem>>>(se, gaf, lab, b1, b2, lw, lb, out);
}

// round 8
// speedup vs baseline: 1.0823x; 1.0823x over previous
#include <cuda_runtime.h>
#include <cstdint>
#include <math.h>

// Shapes (fixed by the problem)
#define NSENT 4096
#define L     512
#define LQ    32
#define D     30
#define AF    10
#define KK    4

#define TILE_FLOATS  (L * D)        // 15360
#define CHUNK_FLOATS 3840           // 128 rows * 30
#define CHUNK_BYTES  (CHUNK_FLOATS * 4)
#define NSLOTS 3
#define NCTAS  444                  // 148 SMs * 3, single wave
#define TPB    480

// Precomputed tables / question-side results
__device__ float g_W1sum[D * D];
__device__ float g_W2sum[D * D];
__device__ float g_A1[D * D * 6];
__device__ float g_qraw[D];
__device__ float g_q1g[D];
__device__ float g_q2g[D];
__device__ float g_inv_nraw, g_inv_n1, g_inv_n2;
__device__ float g_costs[NSENT];
__device__ int   g_ctr;

__device__ __forceinline__ uint32_t smem_u32(const void* p) {
    uint32_t a;
    asm("{ .reg .u64 t; cvta.to.shared.u64 t, %1; cvt.u32.u64 %0, t; }" : "=r"(a) : "l"(p));
    return a;
}

__device__ __forceinline__ void mbar_wait(uint32_t bar_a, uint32_t parity) {
    uint32_t done;
    asm volatile(
        "{\n\t.reg .pred p;\n\t"
        "mbarrier.try_wait.parity.acquire.cta.shared::cta.b64 p, [%1], %2;\n\t"
        "selp.b32 %0, 1, 0, p;\n\t}"
        : "=r"(done) : "r"(bar_a), "r"(parity) : "memory");
    if (!done) {
        asm volatile(
            "{\n\t.reg .pred P1;\n\t"
            "WL_%=:\n\t"
            "mbarrier.try_wait.parity.acquire.cta.shared::cta.b64 P1, [%0], %1, 0x989680;\n\t"
            "@P1 bra.uni WD_%=;\n\t"
            "bra.uni WL_%=;\n\t"
            "WD_%=:\n\t}"
            :: "r"(bar_a), "r"(parity) : "memory");
    }
}

// ---------------------------------------------------------------------------
// Kernel 1 (prep): tables into gmem; question side from SMEM.
// ---------------------------------------------------------------------------
__global__ void prep_kernel(const float* __restrict__ qe,
                            const float* __restrict__ w1, const float* __restrict__ b1,
                            const float* __restrict__ w2, const float* __restrict__ b2)
{
    __shared__ float sW1[D * D], sW2[D * D], sA[D * D * 6];
    __shared__ float Sq[32], xbq[6][32], Tq[32];

    int tid = threadIdx.x; // 960
    if (tid == 0) g_ctr = 0;

    if (tid < D * D) {
        const float* w = w1 + tid * KK;
        float w0 = w[0], wv1 = w[1], wv2 = w[2], w3 = w[3];
        float ws = w0 + wv1 + wv2 + w3;
        sW1[tid] = ws; g_W1sum[tid] = ws;
        const float* v = w2 + tid * KK;
        float vs = v[0] + v[1] + v[2] + v[3];
        sW2[tid] = vs; g_W2sum[tid] = vs;
        float a0 = 3.f * w3 + 2.f * wv2 + wv1;
        float a1 = 2.f * w3 + wv2;
        float a2 = w3;
        float a3 = w0;
        float a4 = 2.f * w0 + wv1;
        float a5 = 3.f * w0 + 2.f * wv1 + wv2;
        float* As = sA + tid * 6;  float* Ag = g_A1 + tid * 6;
        As[0] = a0; Ag[0] = a0;  As[1] = a1; Ag[1] = a1;
        As[2] = a2; Ag[2] = a2;  As[3] = a3; Ag[3] = a3;
        As[4] = a4; Ag[4] = a4;  As[5] = a5; Ag[5] = a5;
    }

    if (tid < D) {
        float s = 0.f;
        for (int t = 0; t < LQ; t++) s += qe[t * D + tid];
        Sq[tid] = s;
        xbq[0][tid] = qe[0 * D + tid];
        xbq[1][tid] = qe[1 * D + tid];
        xbq[2][tid] = qe[2 * D + tid];
        xbq[3][tid] = qe[(LQ - 3) * D + tid];
        xbq[4][tid] = qe[(LQ - 2) * D + tid];
        xbq[5][tid] = qe[(LQ - 1) * D + tid];
    }
    __syncthreads();

    if (tid < 32) {
        const int o = tid;
        const float invLq3 = 1.f / (float)(LQ + 3);
        float q1 = 0.f, Tv = 0.f;
        if (o < D) {
            float ds = 0.f, bc = 0.f;
            for (int j = 0; j < D; j++) ds += sW1[o * D + j] * Sq[j];
            for (int j = 0; j < D; j++) {
                const float* A = sA + (o * D + j) * 6;
                #pragma unroll
                for (int m = 0; m < 6; m++) bc += A[m] * xbq[m][j];
            }
            q1 = b1[o] + ds * invLq3;
            Tv = (float)LQ * b1[o] + ds - 0.25f * bc;
        }
        Tq[o] = Tv;
        __syncwarp();

        float q2 = 0.f;
        if (o < D) {
            float d2 = 0.f;
            for (int j = 0; j < D; j++) d2 += sW2[o * D + j] * Tq[j];
            q2 = b2[o] + d2 * invLq3;
            g_qraw[o] = Sq[o];
            g_q1g[o] = q1;
            g_q2g[o] = q2;
        }
        __syncwarp();

        float n0 = (o < D) ? Sq[o] * Sq[o] : 0.f;
        float n1 = q1 * q1;
        float n2 = q2 * q2;
        #pragma unroll
        for (int off = 16; off; off >>= 1) {
            n0 += __shfl_down_sync(0xffffffffu, n0, off);
            n1 += __shfl_down_sync(0xffffffffu, n1, off);
            n2 += __shfl_down_sync(0xffffffffu, n2, off);
        }
        if (o == 0) {
            g_inv_nraw = rsqrtf(n0);
            g_inv_n1 = rsqrtf(n1);
            g_inv_n2 = rsqrtf(n2);
        }
    }
}

// ---------------------------------------------------------------------------
// Persistent fused kernel: 3-slot TMA chunk pipeline + in-smem reduce + tail.
// ---------------------------------------------------------------------------
__global__ __launch_bounds__(TPB, 3) void fused_kernel(
    const float* __restrict__ se, const float* __restrict__ gaf,
    const int* __restrict__ labels,
    const float* __restrict__ b1, const float* __restrict__ b2,
    const float* __restrict__ lw, const float* __restrict__ lb,
    float* __restrict__ out)
{
    extern __shared__ float dyn[];
    float* slots    = dyn;                          // [NSLOTS][CHUNK_FLOATS]
    float* partials = dyn + NSLOTS * CHUNK_FLOATS;  // [2][1920]

    __shared__ __align__(8) uint64_t mbar[NSLOTS];
    __shared__ float xb[2][6 * 32];
    __shared__ float S[32], T[32];
    __shared__ int last;

    const int bid = blockIdx.x;
    const int tid = threadIdx.x;
    const int count = (NSENT - bid + NCTAS - 1) / NCTAS;  // sentences for this CTA
    const int total = count * 4;                           // chunks

    if (tid == 0) {
        #pragma unroll
        for (int s = 0; s < NSLOTS; s++)
            asm volatile("mbarrier.init.shared.b64 [%0], %1;"
                         :: "r"(smem_u32(&mbar[s])), "r"(1) : "memory");
    }
    __syncthreads();

    // Prologue: fill the pipeline
    if (tid == 0) {
        #pragma unroll
        for (int c = 0; c < NSLOTS; c++) {
            int i = c >> 2, k = c & 3;
            int n = bid + i * NCTAS;
            const float* src = se + (size_t)n * TILE_FLOATS + k * CHUNK_FLOATS;
            uint32_t bar_a = smem_u32(&mbar[c]);
            uint32_t dst_a = smem_u32(slots + c * CHUNK_FLOATS);
            asm volatile("mbarrier.arrive.expect_tx.shared.b64 _, [%0], %1;"
                         :: "r"(bar_a), "r"((uint32_t)CHUNK_BYTES) : "memory");
            asm volatile("cp.async.bulk.shared::cta.global.mbarrier::complete_tx::bytes [%0], [%1], %2, [%3];"
                         :: "r"(dst_a), "l"(src), "r"((uint32_t)CHUNK_BYTES), "r"(bar_a) : "memory");
        }
    }

    float4 acc = make_float4(0.f, 0.f, 0.f, 0.f);

    for (int c = 0; c < total; c++) {
        const int slot = c % NSLOTS;
        const uint32_t parity = (uint32_t)((c / NSLOTS) & 1);
        const int k = c & 3;
        const int i = c >> 2;
        const int sp = i & 1;

        mbar_wait(smem_u32(&mbar[slot]), parity);

        const float* sb = slots + slot * CHUNK_FLOATS;
        {
            float4 v0 = reinterpret_cast<const float4*>(sb)[tid];
            float4 v1 = reinterpret_cast<const float4*>(sb)[tid + TPB];
            acc.x += v0.x + v1.x;
            acc.y += v0.y + v1.y;
            acc.z += v0.z + v1.z;
            acc.w += v0.w + v1.w;
        }
        if (k == 0 && tid < 3 * D)
            xb[sp][(tid / D) * 32 + tid % D] = sb[tid];
        if (k == 3) {
            if (tid < 3 * D)
                xb[sp][(3 + tid / D) * 32 + tid % D] = sb[3 * CHUNK_FLOATS / 4 + 90 - 90 + 3750 + tid - tid + tid];  // placeholder removed below
        }
        if (k == 3) {
            if (tid < 3 * D)
                xb[sp][(3 + tid / D) * 32 + tid % D] = sb[3750 + tid];
            reinterpret_cast<float4*>(partials + sp * (4 * TPB))[tid] = acc;
            acc = make_float4(0.f, 0.f, 0.f, 0.f);
        }
        __syncthreads();   // all consumed slot; partials/xb visible

        // Refill this slot with chunk c+NSLOTS
        if (tid == 0 && c + NSLOTS < total) {
            int cn = c + NSLOTS;
            int ni = cn >> 2, nk = cn & 3;
            int n = bid + ni * NCTAS;
            const float* src = se + (size_t)n * TILE_FLOATS + nk * CHUNK_FLOATS;
            uint32_t bar_a = smem_u32(&mbar[slot]);
            uint32_t dst_a = smem_u32(slots + slot * CHUNK_FLOATS);
            asm volatile("mbarrier.arrive.expect_tx.shared.b64 _, [%0], %1;"
                         :: "r"(bar_a), "r"((uint32_t)CHUNK_BYTES) : "memory");
            asm volatile("cp.async.bulk.shared::cta.global.mbarrier::complete_tx::bytes [%0], [%1], %2, [%3];"
                         :: "r"(dst_a), "l"(src), "r"((uint32_t)CHUNK_BYTES), "r"(bar_a) : "memory");
        }

        // Sentence finished: warp 0 does the tail while others stream on
        if (k == 3 && tid < 32) {
            const int o = tid;
            const int n = bid + i * NCTAS;
            const float* part = partials + sp * (4 * TPB);

            float s = 0.f;
            if (o < D) {
                #pragma unroll
                for (int q = 0; q < (TPB * 4) / D; q++)  // 64 partials, stride 30
                    s += part[o + D * q];
            }
            S[o] = s;
            __syncwarp();

            const float inv515 = 1.f / (float)(L + 3);
            float s1 = 0.f, Tv = 0.f;
            if (o < D) {
                float ds = 0.f, bc = 0.f;
                #pragma unroll
                for (int j = 0; j < D; j++) ds += g_W1sum[o * D + j] * S[j];
                #pragma unroll
                for (int j = 0; j < D; j++) {
                    const float* A = g_A1 + (o * D + j) * 6;
                    #pragma unroll
                    for (int m = 0; m < 6; m++) bc += A[m] * xb[sp][m * 32 + j];
                }
                s1 = b1[o] + ds * inv515;
                Tv = (float)L * b1[o] + ds - 0.25f * bc;
            }
            T[o] = Tv;
            __syncwarp();

            float s2 = 0.f;
            if (o < D) {
                float d2 = 0.f;
                #pragma unroll
                for (int j = 0; j < D; j++) d2 += g_W2sum[o * D + j] * T[j];
                s2 = b2[o] + d2 * inv515;
            }

            float qr = 0.f, q1v = 0.f, q2v = 0.f;
            if (o < D) { qr = g_qraw[o]; q1v = g_q1g[o]; q2v = g_q2g[o]; }

            float p0 = s * qr, p1 = s * q2v, p2 = s * s;
            float p3 = s1 * q1v, p4 = s1 * s1, p5 = s2 * q2v, p6 = s2 * s2;
            #pragma unroll
            for (int off = 16; off; off >>= 1) {
                p0 += __shfl_down_sync(0xffffffffu, p0, off);
                p1 += __shfl_down_sync(0xffffffffu, p1, off);
                p2 += __shfl_down_sync(0xffffffffu, p2, off);
                p3 += __shfl_down_sync(0xffffffffu, p3, off);
                p4 += __shfl_down_sync(0xffffffffu, p4, off);
                p5 += __shfl_down_sync(0xffffffffu, p5, off);
                p6 += __shfl_down_sync(0xffffffffu, p6, off);
            }
            if (o == 0) {
                float inv_nS = rsqrtf(p2);
                float sim1 = (n == 0) ? (p0 * g_inv_nraw * inv_nS)
                                      : (p1 * g_inv_n2 * inv_nS);
                float sim2 = p3 * rsqrtf(p4) * g_inv_n1;
                float sim3 = p5 * rsqrtf(p6) * g_inv_n2;

                const float* g = gaf + (size_t)n * AF;
                float l0 = lb[0] + lw[0] * sim1 + lw[1] * sim2 + lw[2] * sim3;
                float l1 = lb[1] + lw[13] * sim1 + lw[14] * sim2 + lw[15] * sim3;
                #pragma unroll
                for (int f = 0; f < AF; f++) {
                    float gv = g[f];
                    l0 += lw[3 + f] * gv;
                    l1 += lw[16 + f] * gv;
                }
                float mx = fmaxf(l0, l1);
                float lse = mx + logf(expf(l0 - mx) + expf(l1 - mx));
                float lp0 = l0 - lse, lp1 = l1 - lse;
                float e0 = expf(lp0), e1 = expf(lp1);
                out[1 + n] = e1 / (e0 + e1);
                int lab = labels[n];
                g_costs[n] = -(lab ? lp1 : lp0);
            }
        }
    }

    // Last CTA: deterministic cost reduction
    __syncthreads();
    if (tid == 0) {
        __threadfence();
        int old = atomicAdd(&g_ctr, 1);
        last = (old == NCTAS - 1) ? 1 : 0;
    }
    __syncthreads();
    if (last) {
        __threadfence();
        __shared__ float sm[256];
        if (tid < 256) {
            float s = 0.f;
            for (int i2 = tid; i2 < NSENT; i2 += 256) s += g_costs[i2];
            sm[tid] = s;
        }
        __syncthreads();
        for (int w = 128; w; w >>= 1) {
            if (tid < w) sm[tid] += sm[tid + w];
            __syncthreads();
        }
        if (tid == 0) out[0] = sm[0] / (float)NSENT;
    }
}

// ---------------------------------------------------------------------------
extern "C" void kernel_launch(void* const* d_in, const int* in_sizes, int n_in,
                              void* d_out, int out_size)
{
    const float* se  = (const float*)d_in[0];
    const float* qe  = (const float*)d_in[1];
    const float* gaf = (const float*)d_in[2];
    const int*   lab = (const int*)d_in[3];
    const float* w1  = (const float*)d_in[4];
    const float* b1  = (const float*)d_in[5];
    const float* w2  = (const float*)d_in[6];
    const float* b2  = (const float*)d_in[7];
    const float* lw  = (const float*)d_in[8];
    const float* lb  = (const float*)d_in[9];
    float* out = (float*)d_out;

    const int dyn_smem = (NSLOTS * CHUNK_FLOATS + 2 * 4 * TPB) * 4;  // slots + partials
    static int configured = 0;
    if (!configured) {
        cudaFuncSetAttribute(fused_kernel, cudaFuncAttributeMaxDynamicSharedMemorySize, dyn_smem);
        configured = 1;
    }

    prep_kernel<<<1, 960>>>(qe, w1, b1, w2, b2);
    fused_kernel<<<NCTAS, TPB, dyn_smem>>>(se, gaf, lab, b1, b2, lw, lb, out);
}